// round 17
// baseline (speedup 1.0000x reference)
#include <cuda_runtime.h>
#include <cuda_fp16.h>
#include <cstdint>

#define BATCH 8
#define HH    64
#define WW_   64
#define TT    4096
#define CC    256
#define DD    512
#define MM    (BATCH * TT)   // 32768

#define NCHAIN 4096
#define NCHUNK 32
#define CHLEN  128

// ---------------- scratch (static device globals; no runtime alloc) ----------
__device__ float  g_comb[25 * CC];
__device__ __half g_xfh[MM * CC];           // fp16 activations (GEMM A)
__device__ __half g_kh [MM * CC];           // fp16 GEMM outputs (wkv inputs)
__device__ __half g_vh [MM * CC];
__device__ __half g_srh[MM * CC];
__device__ __half g_xsh[MM * DD];           // fp16 scan output (GEMM A)
__device__ float  g_sa[NCHUNK * NCHAIN];
__device__ float  g_sb[NCHUNK * NCHAIN];
__device__ float  g_sp[NCHUNK * NCHAIN];
__device__ float  g_pa[NCHUNK * NCHAIN];
__device__ float  g_pb[NCHUNK * NCHAIN];
__device__ float  g_pp[NCHUNK * NCHAIN];
// fp16 weights (K-major, W[n][k])
__device__ __half g_wkh[CC * CC];
__device__ __half g_wvh[CC * CC];
__device__ __half g_wrh[CC * CC];
__device__ __half g_woh[CC * DD];

__device__ __forceinline__ void cp16(unsigned dst, const void* src) {
    asm volatile("cp.async.ca.shared.global [%0], [%1], 16;" :: "r"(dst), "l"(src));
}
#define CP_COMMIT() asm volatile("cp.async.commit_group;" ::: "memory")
#define CP_WAIT1()  asm volatile("cp.async.wait_group 1;"  ::: "memory")

// ---------------- 0) round weights to fp16 -----------------------------------
__global__ void round_weights_kernel(const float* __restrict__ Wk,
                                     const float* __restrict__ Wv,
                                     const float* __restrict__ Wr,
                                     const float* __restrict__ Wo)
{
    int i = blockIdx.x * 256 + threadIdx.x;
    if (i < CC * CC) {
        g_wkh[i] = __float2half_rn(Wk[i]);
        g_wvh[i] = __float2half_rn(Wv[i]);
        g_wrh[i] = __float2half_rn(Wr[i]);
    }
    if (i < CC * DD) g_woh[i] = __float2half_rn(Wo[i]);
}

// ---------------- 1) combine identity + 1x1 + 3x3 + 5x5 into one 5x5 ---------
__global__ void combine_weights_kernel(const float* __restrict__ alpha,
                                       const float* __restrict__ cw1,
                                       const float* __restrict__ cw3,
                                       const float* __restrict__ cw5)
{
    int c = threadIdx.x;
    float a0 = alpha[0], a1 = alpha[1], a2 = alpha[2], a3 = alpha[3];
    #pragma unroll
    for (int j = 0; j < 5; j++) {
        #pragma unroll
        for (int i = 0; i < 5; i++) {
            float v = a3 * cw5[c * 25 + j * 5 + i];
            if (j >= 1 && j <= 3 && i >= 1 && i <= 3)
                v += a2 * cw3[c * 9 + (j - 1) * 3 + (i - 1)];
            if (j == 2 && i == 2)
                v += a1 * cw1[c] + a0;
            g_comb[(j * 5 + i) * CC + c] = v;
        }
    }
}

// ---------------- 2) depthwise 5x5 conv, 4 output cols/block, fp16 out -------
__global__ __launch_bounds__(256) void omni_conv_kernel(const float* __restrict__ x)
{
    int b   = blockIdx.x >> 4;
    int xp  = blockIdx.x & 15;
    int xc0 = xp * 4;
    int c   = threadIdx.x;

    float wgt[25];
    #pragma unroll
    for (int j = 0; j < 25; j++) wgt[j] = g_comb[j * CC + c];

    const float* xin  = x     + (size_t)b * TT * CC + c;
    __half*      xout = g_xfh + (size_t)b * TT * CC + (size_t)xc0 * CC + c;

    float win[5][8];
    #pragma unroll
    for (int i = 0; i < 8; i++) { win[0][i] = 0.f; win[1][i] = 0.f; }
    #pragma unroll
    for (int r = 0; r < 3; r++) {
        #pragma unroll
        for (int i = 0; i < 8; i++) {
            int xx = xc0 - 2 + i;
            win[2 + r][i] = (xx >= 0 && xx < WW_) ? xin[((size_t)r * WW_ + xx) * CC] : 0.f;
        }
    }

    for (int y = 0; y < HH; y++) {
        float acc0 = 0.f, acc1 = 0.f, acc2 = 0.f, acc3 = 0.f;
        #pragma unroll
        for (int j = 0; j < 5; j++)
            #pragma unroll
            for (int i = 0; i < 5; i++) {
                float w = wgt[j * 5 + i];
                acc0 = fmaf(w, win[j][i],     acc0);
                acc1 = fmaf(w, win[j][i + 1], acc1);
                acc2 = fmaf(w, win[j][i + 2], acc2);
                acc3 = fmaf(w, win[j][i + 3], acc3);
            }
        size_t ro = (size_t)y * WW_ * CC;
        xout[ro]          = __float2half_rn(acc0);
        xout[ro + CC]     = __float2half_rn(acc1);
        xout[ro + 2 * CC] = __float2half_rn(acc2);
        xout[ro + 3 * CC] = __float2half_rn(acc3);

        #pragma unroll
        for (int j = 0; j < 4; j++)
            #pragma unroll
            for (int i = 0; i < 8; i++) win[j][i] = win[j + 1][i];
        int row = y + 3;
        #pragma unroll
        for (int i = 0; i < 8; i++) {
            int xx = xc0 - 2 + i;
            win[4][i] = (row < HH && xx >= 0 && xx < WW_)
                        ? xin[((size_t)row * WW_ + xx) * CC] : 0.f;
        }
    }
}

// ---------------- 3) fp16 m16n8k16 GEMM + ldmatrix + cp.async 3-stage --------
// houts=1: fp16 output (k/v/sr); houts=0: fp32 output (final projection).
#define SH_   20
#define STW   (128 * SH_)                   // u32 per matrix per stage
#define GS_BYTES (6 * STW * 4)              // 3 stages x (A+B) = 61440

__device__ __forceinline__ void ldsm4(unsigned& r0, unsigned& r1,
                                      unsigned& r2, unsigned& r3, unsigned addr)
{
    asm volatile("ldmatrix.sync.aligned.m8n8.x4.shared.b16 {%0,%1,%2,%3}, [%4];"
                 : "=r"(r0), "=r"(r1), "=r"(r2), "=r"(r3) : "r"(addr));
}

__global__ __launch_bounds__(256, 2) void gemm_qkv_kernel(
    const __half* __restrict__ A,
    const __half* __restrict__ W0, const __half* __restrict__ W1,
    const __half* __restrict__ W2,
    void* __restrict__ O0, void* __restrict__ O1, void* __restrict__ O2,
    int K, int actsel, int houts)
{
    extern __shared__ unsigned gsm[];
    const unsigned smemB = (unsigned)__cvta_generic_to_shared(gsm);
    const int tid = threadIdx.x;
    const int grp = blockIdx.x >> 1;               // 0..2 weight/output select
    const int bn  = (blockIdx.x & 1) * 128;
    const __half* W = (grp == 0) ? W0 : (grp == 1) ? W1 : W2;
    void*       Out = (grp == 0) ? O0 : (grp == 1) ? O1 : O2;
    const int act = (actsel >> grp) & 1;
    const size_t bm = (size_t)blockIdx.y * 128;

    const int lane = tid & 31, wid = tid >> 5;
    const int wm = (wid & 1) * 64;
    const int wn = (wid >> 1) * 32;
    const int qr = lane >> 2;
    const int qc = lane & 3;

    const unsigned aLane = (unsigned)(((wm + (lane & 15)) * SH_ + (lane >> 4) * 4) * 4);
    const unsigned bLane = (unsigned)(((wn + (lane & 7) + (lane >> 4) * 8) * SH_
                                       + ((lane >> 3) & 1) * 4) * 4);

    const int srow = tid & 127;
    const int sh   = tid >> 7;
    const __half* Ag = A + (bm + srow) * (size_t)K + sh * 16;
    const __half* Wg = W + (size_t)(bn + srow) * K + sh * 16;
    const unsigned dRow = smemB + (unsigned)((srow * SH_ + sh * 8) * 4);

    const int NT = K >> 5;

    float acc[4][4][4];
    #pragma unroll
    for (int mf = 0; mf < 4; mf++)
        #pragma unroll
        for (int nf = 0; nf < 4; nf++)
            #pragma unroll
            for (int i = 0; i < 4; i++) acc[mf][nf][i] = 0.f;

    #pragma unroll
    for (int s = 0; s < 2; s++) {
        const unsigned off = (unsigned)(s * 2 * STW) * 4u;
        const __half* a = Ag + s * 32;
        const __half* w = Wg + s * 32;
        cp16(dRow + off,      a);
        cp16(dRow + off + 16, a + 8);
        cp16(dRow + off + (unsigned)STW * 4u,      w);
        cp16(dRow + off + (unsigned)STW * 4u + 16, w + 8);
        CP_COMMIT();
    }

    for (int kt = 0; kt < NT; kt++) {
        CP_WAIT1();
        __syncthreads();

        if (kt + 2 < NT) {
            const int st = (kt + 2) % 3;
            const unsigned off = (unsigned)(st * 2 * STW) * 4u;
            const __half* a = Ag + (kt + 2) * 32;
            const __half* w = Wg + (kt + 2) * 32;
            cp16(dRow + off,      a);
            cp16(dRow + off + 16, a + 8);
            cp16(dRow + off + (unsigned)STW * 4u,      w);
            cp16(dRow + off + (unsigned)STW * 4u + 16, w + 8);
        }
        CP_COMMIT();

        const unsigned stA = smemB + (unsigned)((kt % 3) * 2 * STW) * 4u;
        const unsigned stB = stA + (unsigned)STW * 4u;

        #pragma unroll
        for (int s = 0; s < 2; s++) {
            const unsigned so = (unsigned)(s * 8) * 4u;
            unsigned b0[4], b1[4];
            ldsm4(b0[0], b1[0], b0[1], b1[1], stB + bLane + so);
            ldsm4(b0[2], b1[2], b0[3], b1[3], stB + bLane + so + (unsigned)(16 * SH_ * 4));
            #pragma unroll
            for (int mf = 0; mf < 4; mf++) {
                unsigned a0, a1, a2, a3;
                ldsm4(a0, a1, a2, a3,
                      stA + aLane + so + (unsigned)(mf * 16 * SH_ * 4));
                #pragma unroll
                for (int nf = 0; nf < 4; nf++) {
                    asm volatile(
                        "mma.sync.aligned.m16n8k16.row.col.f32.f16.f16.f32 "
                        "{%0,%1,%2,%3}, {%4,%5,%6,%7}, {%8,%9}, {%0,%1,%2,%3};"
                        : "+f"(acc[mf][nf][0]), "+f"(acc[mf][nf][1]),
                          "+f"(acc[mf][nf][2]), "+f"(acc[mf][nf][3])
                        : "r"(a0), "r"(a1), "r"(a2), "r"(a3),
                          "r"(b0[nf]), "r"(b1[nf]));
                }
            }
        }
    }

    #pragma unroll
    for (int mf = 0; mf < 4; mf++) {
        size_t r0 = bm + wm + mf * 16 + qr;
        #pragma unroll
        for (int nf = 0; nf < 4; nf++) {
            int col = bn + wn + nf * 8 + qc * 2;
            float c0 = acc[mf][nf][0], c1 = acc[mf][nf][1];
            float c2 = acc[mf][nf][2], c3 = acc[mf][nf][3];
            if (act) {
                c0 = 1.0f / (1.0f + __expf(-c0));
                c1 = 1.0f / (1.0f + __expf(-c1));
                c2 = 1.0f / (1.0f + __expf(-c2));
                c3 = 1.0f / (1.0f + __expf(-c3));
            }
            if (houts) {
                __half* Oh = (__half*)Out;
                *(__half2*)(Oh + r0 * 256 + col)       = __floats2half2_rn(c0, c1);
                *(__half2*)(Oh + (r0 + 8) * 256 + col) = __floats2half2_rn(c2, c3);
            } else {
                float* Of = (float*)Out;
                *(float2*)(Of + r0 * 256 + col)       = make_float2(c0, c1);
                *(float2*)(Of + (r0 + 8) * 256 + col) = make_float2(c2, c3);
            }
        }
    }
}

// ---------------- 4) WKV chunk-parallel scan (fp16 inputs) -------------------
__device__ __forceinline__ void wkv_state(float kt, float vt, float wdec,
                                          float& a, float& b, float& pp)
{
    float ww2 = pp + wdec;
    float d2  = ww2 - kt;
    float f   = __expf(-fabsf(d2));
    float f1  = (d2 >= 0.f) ? 1.f : f;
    float f2  = (d2 >= 0.f) ? f : 1.f;
    a  = f1 * a + f2 * vt;
    b  = f1 * b + f2;
    pp = fmaxf(ww2, kt);
}

__global__ __launch_bounds__(256) void wkv_pass1(const float* __restrict__ sd)
{
    int g     = blockIdx.x * 256 + threadIdx.x;
    int chain = g & (NCHAIN - 1);
    int chunk = g >> 12;
    int b = chain >> 9;
    int d = chain & 511;
    int c = d & 255;
    bool second = d >= 256;

    float wdec = -__expf(sd[d] * (1.0f / (float)TT));
    const size_t base = (size_t)b * TT * CC + c;

    float a = 0.f, bb = 0.f, pp = -1e38f;
    int tstart = chunk * CHLEN;

    for (int t0 = tstart; t0 < tstart + CHLEN; t0 += 8) {
        float kb[8], vb[8];
        #pragma unroll
        for (int i = 0; i < 8; i++) {
            int t  = t0 + i;
            int ti = second ? (((t & 63) << 6) | (t >> 6)) : t;
            size_t off = base + (size_t)ti * CC;
            kb[i] = __half2float(g_kh[off]);
            vb[i] = __half2float(g_vh[off]);
        }
        #pragma unroll
        for (int i = 0; i < 8; i++)
            wkv_state(kb[i], vb[i], wdec, a, bb, pp);
    }
    g_sa[chunk * NCHAIN + chain] = a;
    g_sb[chunk * NCHAIN + chain] = bb;
    g_sp[chunk * NCHAIN + chain] = pp;
}

__global__ __launch_bounds__(256) void wkv_pass2(const float* __restrict__ sd)
{
    int chain = blockIdx.x * 256 + threadIdx.x;
    int d = chain & 511;
    float wdec = -__expf(sd[d] * (1.0f / (float)TT));
    float Lw = (float)CHLEN * wdec;

    float A = 0.f, B = 0.f, P = -1e38f;
    for (int j = 0; j < NCHUNK; j++) {
        g_pa[j * NCHAIN + chain] = A;
        g_pb[j * NCHAIN + chain] = B;
        g_pp[j * NCHAIN + chain] = P;
        float ca = g_sa[j * NCHAIN + chain];
        float cb = g_sb[j * NCHAIN + chain];
        float cp = g_sp[j * NCHAIN + chain];
        float np = P + Lw;
        float p  = fmaxf(np, cp);
        float e1 = __expf(np - p);
        float e2 = __expf(cp - p);
        A = e1 * A + e2 * ca;
        B = e1 * B + e2 * cb;
        P = p;
    }
}

__global__ __launch_bounds__(256) void wkv_pass3(const float* __restrict__ sd,
                                                 const float* __restrict__ sf)
{
    int g     = blockIdx.x * 256 + threadIdx.x;
    int chain = g & (NCHAIN - 1);
    int chunk = g >> 12;
    int b = chain >> 9;
    int d = chain & 511;
    int c = d & 255;
    bool second = d >= 256;

    float wdec = -__expf(sd[d] * (1.0f / (float)TT));
    float u    =  sf[d] * (1.0f / (float)TT);

    const size_t base = (size_t)b * TT * CC + c;
    __half* xsp = g_xsh + (size_t)b * TT * DD + d;

    float a  = g_pa[chunk * NCHAIN + chain];
    float bb = g_pb[chunk * NCHAIN + chain];
    float pp = g_pp[chunk * NCHAIN + chain];

    int tstart = chunk * CHLEN;
    for (int t0 = tstart; t0 < tstart + CHLEN; t0 += 8) {
        float kb[8], vb[8], sb[8];
        #pragma unroll
        for (int i = 0; i < 8; i++) {
            int t  = t0 + i;
            int ti = second ? (((t & 63) << 6) | (t >> 6)) : t;
            size_t off = base + (size_t)ti * CC;
            kb[i] = __half2float(g_kh[off]);
            vb[i] = __half2float(g_vh[off]);
            sb[i] = __half2float(g_srh[base + (size_t)t * CC]);
        }
        #pragma unroll
        for (int i = 0; i < 8; i++) {
            float kt = kb[i], vt = vb[i];
            float ww = u + kt;
            float d1 = pp - ww;
            float e  = __expf(-fabsf(d1));
            float e1 = (d1 >= 0.f) ? 1.f : e;
            float e2 = (d1 >= 0.f) ? e : 1.f;
            float out = __fdividef(e1 * a + e2 * vt, e1 * bb + e2);
            wkv_state(kt, vt, wdec, a, bb, pp);
            xsp[(size_t)(t0 + i) * DD] = __float2half_rn(out * sb[i]);
        }
    }
}

// ---------------- launch -----------------------------------------------------
extern "C" void kernel_launch(void* const* d_in, const int* in_sizes, int n_in,
                              void* d_out, int out_size)
{
    const float* x     = (const float*)d_in[0];
    const float* alpha = (const float*)d_in[1];
    const float* cw1   = (const float*)d_in[2];
    const float* cw3   = (const float*)d_in[3];
    const float* cw5   = (const float*)d_in[4];
    const float* Wk    = (const float*)d_in[5];
    const float* Wv    = (const float*)d_in[6];
    const float* Wr    = (const float*)d_in[7];
    const float* Wo    = (const float*)d_in[8];
    const float* sd    = (const float*)d_in[9];
    const float* sf    = (const float*)d_in[10];

    __half *xfh, *kh, *vh, *srh, *xsh, *wkh, *wvh, *wrh, *woh;
    cudaGetSymbolAddress((void**)&xfh, g_xfh);
    cudaGetSymbolAddress((void**)&kh,  g_kh);
    cudaGetSymbolAddress((void**)&vh,  g_vh);
    cudaGetSymbolAddress((void**)&srh, g_srh);
    cudaGetSymbolAddress((void**)&xsh, g_xsh);
    cudaGetSymbolAddress((void**)&wkh, g_wkh);
    cudaGetSymbolAddress((void**)&wvh, g_wvh);
    cudaGetSymbolAddress((void**)&wrh, g_wrh);
    cudaGetSymbolAddress((void**)&woh, g_woh);

    cudaFuncSetAttribute(gemm_qkv_kernel,
                         cudaFuncAttributeMaxDynamicSharedMemorySize, GS_BYTES);

    round_weights_kernel<<<(CC * DD + 255) / 256, 256>>>(Wk, Wv, Wr, Wo);
    combine_weights_kernel<<<1, 256>>>(alpha, cw1, cw3, cw5);
    omni_conv_kernel<<<BATCH * 16, 256>>>(x);

    // fused k / v / r(sigmoid) gemms, fp16 outputs
    dim3 g3(6, MM / 128);
    gemm_qkv_kernel<<<g3, 256, GS_BYTES>>>(xfh, wkh, wvh, wrh,
                                           kh, vh, srh, CC, 4, 1);

    wkv_pass1<<<(NCHAIN * NCHUNK) / 256, 256>>>(sd);
    wkv_pass2<<<NCHAIN / 256, 256>>>(sd);
    wkv_pass3<<<(NCHAIN * NCHUNK) / 256, 256>>>(sd, sf);

    // output projection: fp32 output to d_out, K = 512
    dim3 g1(2, MM / 128);
    gemm_qkv_kernel<<<g1, 256, GS_BYTES>>>(xsh, woh, woh, woh,
                                           d_out, d_out, d_out, DD, 0, 0);
}